// round 16
// baseline (speedup 1.0000x reference)
#include <cuda_runtime.h>
#include <cuda.h>
#include <cstdint>

#define B_  16
#define K_  29
#define KP  32
#define C_  512
#define S_  16384
#define SPLIT 16
#define KS (S_ / SPLIT)        // 1024 s per CTA
#define STILE 32               // s per stage (128 B)
#define NT (KS / STILE)        // 32 stages

// ---- TMA kernel smem layout (SW128, row pitch 32 floats = 128 B) ----
#define SWF 32
#define A_FLOATS (128 * SWF)                 // 4096
#define B_FLOATS (KP * SWF)                  // 1024
#define STAGE_FLOATS (A_FLOATS + B_FLOATS)   // 5120
#define STAGE_BYTES (STAGE_FLOATS * 4)       // 20480
#define SMEM_TMA (2 * STAGE_BYTES + 64)      // + 2 mbarriers, 41 KB

// ---- fallback (R14) smem layout ----
#define STRIDE 36
#define AF_FB (128 * STRIDE)
#define BF_FB (KP * STRIDE)
#define STG_FB (AF_FB + BF_FB)
#define SMEM_FB (2 * STG_FB * 4)

#define OUTN (B_ * C_ * K_)

// Per (b,k): 1 / sum(exp(x))
__device__ float g_inv[B_ * KP];

// ---------------- helpers ----------------
__device__ __forceinline__ uint32_t s2u(const void* p) {
    return (uint32_t)__cvta_generic_to_shared(p);
}
__device__ __forceinline__ void cp16(uint32_t dst, const void* src) {
    asm volatile("cp.async.cg.shared.global [%0], [%1], 16;" :: "r"(dst), "l"(src));
}
__device__ __forceinline__ uint32_t totf32(float f) {
    uint32_t r;
    asm("cvt.rna.tf32.f32 %0, %1;" : "=r"(r) : "f"(f));
    return r;
}
__device__ __forceinline__ void mma_tf32(float* d, const uint32_t* a,
                                         const uint32_t* b) {
    asm volatile(
        "mma.sync.aligned.m16n8k8.row.col.f32.tf32.tf32.f32 "
        "{%0,%1,%2,%3}, {%4,%5,%6,%7}, {%8,%9}, {%0,%1,%2,%3};"
        : "+f"(d[0]), "+f"(d[1]), "+f"(d[2]), "+f"(d[3])
        : "r"(a[0]), "r"(a[1]), "r"(a[2]), "r"(a[3]), "r"(b[0]), "r"(b[1]));
}
__device__ __forceinline__ void mbar_init(uint32_t a, uint32_t cnt) {
    asm volatile("mbarrier.init.shared.b64 [%0], %1;" :: "r"(a), "r"(cnt) : "memory");
}
__device__ __forceinline__ void mbar_expect(uint32_t a, uint32_t bytes) {
    asm volatile("mbarrier.arrive.expect_tx.shared.b64 _, [%0], %1;"
                 :: "r"(a), "r"(bytes) : "memory");
}
__device__ __forceinline__ void mbar_wait(uint32_t a, uint32_t ph) {
    asm volatile(
        "{\n\t.reg .pred P1;\n\t"
        "WAIT_LOOP_%=:\n\t"
        "mbarrier.try_wait.parity.acquire.cta.shared::cta.b64 P1, [%0], %1, 0x989680;\n\t"
        "@P1 bra.uni WAIT_DONE_%=;\n\t"
        "bra.uni WAIT_LOOP_%=;\n\t"
        "WAIT_DONE_%=:\n\t}"
        :: "r"(a), "r"(ph) : "memory");
}
__device__ __forceinline__ void tma2d(uint32_t smem, const void* tmap,
                                      int cx, int cy, uint32_t mbar) {
    asm volatile(
        "cp.async.bulk.tensor.2d.shared::cta.global.tile.mbarrier::complete_tx::bytes "
        "[%0], [%1, {%2, %3}], [%4];"
        :: "r"(smem), "l"(tmap), "r"(cx), "r"(cy), "r"(mbar) : "memory");
}

// ---------------- kernel 1: zero out + per-(b,k) 1/sum(exp) ----------------
__global__ __launch_bounds__(256) void k1_stats(const float* __restrict__ probs,
                                                float* __restrict__ out) {
    const int k = blockIdx.x, b = blockIdx.y, tid = threadIdx.x;
    const int gsz = gridDim.x * gridDim.y * 256;
    for (int i = (blockIdx.y * gridDim.x + blockIdx.x) * 256 + tid; i < OUTN; i += gsz)
        out[i] = 0.0f;

    const float4* row = (const float4*)(probs + ((size_t)(b * K_ + k)) * S_);
    __shared__ float red[256];

    float s = 0.0f;
#pragma unroll 4
    for (int i = tid; i < S_ / 4; i += 256) {
        float4 v = row[i];
        s += __expf(v.x) + __expf(v.y) + __expf(v.z) + __expf(v.w);
    }
    red[tid] = s;
    __syncthreads();
    for (int off = 128; off > 0; off >>= 1) {
        if (tid < off) red[tid] += red[tid + off];
        __syncthreads();
    }
    if (tid == 0) g_inv[b * KP + k] = 1.0f / red[0];
}

// ---------------- kernel 2 (TMA): exp-GEMM, normalization in epilogue ----------------
// A fragments fed as RAW fp32 bits (HW truncates to tf32) -> zero inner-loop cvts.
// B convert: pure exp + cvt.rna (no per-stage normalization).
// Epilogue: acc * g_inv[k] -> atomicAdd.
__global__ __launch_bounds__(256) void k2_tma(
    const __grid_constant__ CUtensorMap tmA,
    const __grid_constant__ CUtensorMap tmB,
    float* __restrict__ out) {
    extern __shared__ float sh[];

    const int tid  = threadIdx.x;
    const int warp = tid >> 5, lane = tid & 31;
    const int b    = blockIdx.z;
    const int cblk = blockIdx.y;
    const int bx   = blockIdx.x;

    const int r = lane >> 2, q = lane & 3;
    const int c0 = warp * 16;

    const int frow = tid >> 3;          // B convert row (0..31)
    const int fcol = tid & 7;           // 16B chunk
    const int fswz = fcol ^ (frow & 7); // swizzled chunk

    const uint32_t sb = s2u(sh);
    const uint32_t MB = sb + 2 * STAGE_BYTES;
    const int rowA0 = b * C_ + cblk * 128;
    const int rowB0 = b * K_;           // rows 29..31 cross-batch/OOB -> discarded cols

    if (tid == 0) { mbar_init(MB, 1); mbar_init(MB + 8, 1); }
    __syncthreads();

    if (tid == 0) {
        asm volatile("fence.proxy.async.shared::cta;" ::: "memory");
        mbar_expect(MB, STAGE_BYTES);
        tma2d(sb, &tmA, bx * STILE, rowA0, MB);
        tma2d(sb + A_FLOATS * 4, &tmB, bx * STILE, rowB0, MB);
    }

    float acc[4][4];
#pragma unroll
    for (int n = 0; n < 4; n++)
#pragma unroll
        for (int i = 0; i < 4; i++) acc[n][i] = 0.0f;

    for (int t = 0; t < NT; t++) {
        const int slot = t & 1;
        if (t + 1 < NT && tid == 0) {
            const int ns = slot ^ 1;
            const int soff = ((t + 1) * SPLIT + bx) * STILE;
            asm volatile("fence.proxy.async.shared::cta;" ::: "memory");
            mbar_expect(MB + ns * 8, STAGE_BYTES);
            tma2d(sb + ns * STAGE_BYTES, &tmA, soff, rowA0, MB + ns * 8);
            tma2d(sb + ns * STAGE_BYTES + A_FLOATS * 4, &tmB, soff, rowB0, MB + ns * 8);
        }
        mbar_wait(MB + slot * 8, (t >> 1) & 1);

        float* Ab = sh + slot * STAGE_FLOATS;
        float* Bb = Ab + A_FLOATS;

        // exp + tf32-convert this thread's 16B chunk of B (no normalization)
        {
            float4* bp = (float4*)(Bb + frow * SWF + fswz * 4);
            float4 v = *bp;
            uint4 w;
            w.x = totf32(__expf(v.x));
            w.y = totf32(__expf(v.y));
            w.z = totf32(__expf(v.z));
            w.w = totf32(__expf(v.w));
            *(uint4*)bp = w;
        }
        __syncthreads();   // B conversions + TMA data visible to all warps

        const uint32_t* A = (const uint32_t*)Ab;   // raw fp32 bits as tf32
        const uint32_t* Bm = (const uint32_t*)Bb;
#pragma unroll
        for (int ks = 0; ks < STILE / 8; ks++) {
            const int ch0 = ((2 * ks) ^ r) * 4 + q;       // cols so+q
            const int ch1 = ((2 * ks + 1) ^ r) * 4 + q;   // cols so+q+4
            uint32_t a[4];
            a[0] = A[(c0 + r) * SWF + ch0];
            a[1] = A[(c0 + r + 8) * SWF + ch0];
            a[2] = A[(c0 + r) * SWF + ch1];
            a[3] = A[(c0 + r + 8) * SWF + ch1];
#pragma unroll
            for (int n = 0; n < 4; n++) {
                uint32_t bb[2];
                bb[0] = Bm[(n * 8 + r) * SWF + ch0];
                bb[1] = Bm[(n * 8 + r) * SWF + ch1];
                mma_tf32(acc[n], a, bb);
            }
        }
        __syncthreads();   // slot reads done before reuse
    }

    // ---- epilogue: normalize by 1/sum, then atomicAdd ----
    const int cg = cblk * 128 + c0 + r;
#pragma unroll
    for (int n = 0; n < 4; n++) {
#pragma unroll
        for (int i = 0; i < 4; i++) {
            const int c = cg + (i >> 1) * 8;
            const int k = n * 8 + q * 2 + (i & 1);
            if (k < K_) {
                const float v = acc[n][i] * g_inv[b * KP + k];
                atomicAdd(out + ((size_t)(b * C_ + c)) * K_ + k, v);
            }
        }
    }
}

// ---------------- kernel 2 fallback: cp.async version, same math ----------------
__global__ __launch_bounds__(256) void k2_fb(const float* __restrict__ feats,
                                             const float* __restrict__ probs,
                                             float* __restrict__ out) {
    extern __shared__ float sh[];
    const int tid = threadIdx.x, warp = tid >> 5, lane = tid & 31;
    const int b = blockIdx.z, cblk = blockIdx.y, bx = blockIdx.x;
    const int r = lane >> 2, q = lane & 3, c0 = warp * 16;
    const int frow = tid >> 3, fcol = tid & 7;
    const int kclamp = frow < K_ ? frow : (K_ - 1);
    const float* fbase = feats + ((size_t)(b * C_ + cblk * 128)) * S_;
    const float* pbase = probs + ((size_t)(b * K_ + kclamp)) * S_;
    const uint32_t sh_u = s2u(sh);

    float acc[4][4];
#pragma unroll
    for (int n = 0; n < 4; n++)
#pragma unroll
        for (int i = 0; i < 4; i++) acc[n][i] = 0.0f;

    {
        const int soff = bx * STILE;
#pragma unroll
        for (int i = 0; i < 4; i++) {
            int row = frow + i * 32;
            cp16(sh_u + (row * STRIDE + fcol * 4) * 4,
                 fbase + (size_t)row * S_ + soff + fcol * 4);
        }
        cp16(sh_u + (AF_FB + frow * STRIDE + fcol * 4) * 4, pbase + soff + fcol * 4);
        asm volatile("cp.async.commit_group;");
    }
    for (int t = 0; t < NT; t++) {
        const int buf = t & 1;
        if (t + 1 < NT) {
            const int nbuf = buf ^ 1;
            const int soff = ((t + 1) * SPLIT + bx) * STILE;
#pragma unroll
            for (int i = 0; i < 4; i++) {
                int row = frow + i * 32;
                cp16(sh_u + (nbuf * STG_FB + row * STRIDE + fcol * 4) * 4,
                     fbase + (size_t)row * S_ + soff + fcol * 4);
            }
            cp16(sh_u + (nbuf * STG_FB + AF_FB + frow * STRIDE + fcol * 4) * 4,
                 pbase + soff + fcol * 4);
            asm volatile("cp.async.commit_group;");
            asm volatile("cp.async.wait_group 1;");
        } else {
            asm volatile("cp.async.wait_group 0;");
        }
        float* Ab = sh + buf * STG_FB;
        float* Bb = Ab + AF_FB;
        {
            float4* bp = (float4*)(Bb + frow * STRIDE + fcol * 4);
            float4 v = *bp;
            uint4 w;
            w.x = totf32(__expf(v.x));
            w.y = totf32(__expf(v.y));
            w.z = totf32(__expf(v.z));
            w.w = totf32(__expf(v.w));
            *(uint4*)bp = w;
        }
        __syncthreads();
        const uint32_t* A = (const uint32_t*)Ab;
        const uint32_t* Bm = (const uint32_t*)Bb;
#pragma unroll
        for (int ks = 0; ks < STILE / 8; ks++) {
            const int so = ks * 8;
            uint32_t a[4];
            a[0] = A[(c0 + r) * STRIDE + so + q];
            a[1] = A[(c0 + r + 8) * STRIDE + so + q];
            a[2] = A[(c0 + r) * STRIDE + so + q + 4];
            a[3] = A[(c0 + r + 8) * STRIDE + so + q + 4];
#pragma unroll
            for (int n = 0; n < 4; n++) {
                uint32_t bb[2];
                bb[0] = Bm[(n * 8 + r) * STRIDE + so + q];
                bb[1] = Bm[(n * 8 + r) * STRIDE + so + q + 4];
                mma_tf32(acc[n], a, bb);
            }
        }
        __syncthreads();
    }
    const int cg = cblk * 128 + c0 + r;
#pragma unroll
    for (int n = 0; n < 4; n++) {
#pragma unroll
        for (int i = 0; i < 4; i++) {
            const int c = cg + (i >> 1) * 8;
            const int k = n * 8 + q * 2 + (i & 1);
            if (k < K_) {
                const float v = acc[n][i] * g_inv[b * KP + k];
                atomicAdd(out + ((size_t)(b * C_ + c)) * K_ + k, v);
            }
        }
    }
}

extern "C" void kernel_launch(void* const* d_in, const int* in_sizes, int n_in,
                              void* d_out, int out_size) {
    const float* feats = (const float*)d_in[0];  // (16, 512, 128, 128)
    const float* probs = (const float*)d_in[1];  // (16, 29, 128, 128)
    float* out = (float*)d_out;                  // (16, 512, 29, 1)

    k1_stats<<<dim3(K_, B_), 256>>>(probs, out);

    typedef CUresult (CUDAAPI *EncFn)(
        CUtensorMap*, CUtensorMapDataType, cuuint32_t, void*,
        const cuuint64_t*, const cuuint64_t*, const cuuint32_t*, const cuuint32_t*,
        CUtensorMapInterleave, CUtensorMapSwizzle, CUtensorMapL2promotion,
        CUtensorMapFloatOOBfill);

    void* sym = nullptr;
    cudaDriverEntryPointQueryResult qr = cudaDriverEntryPointSymbolNotFound;
    cudaGetDriverEntryPoint("cuTensorMapEncodeTiled", &sym, cudaEnableDefault, &qr);

    bool ok = false;
    CUtensorMap tmA, tmB;
    if (sym != nullptr && qr == cudaDriverEntryPointSuccess) {
        EncFn enc = (EncFn)sym;
        cuuint64_t dimsA[2] = {(cuuint64_t)S_, (cuuint64_t)(B_ * C_)};
        cuuint64_t strid[1] = {(cuuint64_t)S_ * 4};
        cuuint32_t boxA[2]  = {STILE, 128};
        cuuint32_t ones[2]  = {1, 1};
        CUresult r1 = enc(&tmA, CU_TENSOR_MAP_DATA_TYPE_FLOAT32, 2, (void*)feats,
                          dimsA, strid, boxA, ones,
                          CU_TENSOR_MAP_INTERLEAVE_NONE, CU_TENSOR_MAP_SWIZZLE_128B,
                          CU_TENSOR_MAP_L2_PROMOTION_L2_128B,
                          CU_TENSOR_MAP_FLOAT_OOB_FILL_NONE);
        cuuint64_t dimsB[2] = {(cuuint64_t)S_, (cuuint64_t)(B_ * K_)};
        cuuint32_t boxB[2]  = {STILE, KP};
        CUresult r2 = enc(&tmB, CU_TENSOR_MAP_DATA_TYPE_FLOAT32, 2, (void*)probs,
                          dimsB, strid, boxB, ones,
                          CU_TENSOR_MAP_INTERLEAVE_NONE, CU_TENSOR_MAP_SWIZZLE_128B,
                          CU_TENSOR_MAP_L2_PROMOTION_L2_128B,
                          CU_TENSOR_MAP_FLOAT_OOB_FILL_NONE);
        ok = (r1 == CUDA_SUCCESS) && (r2 == CUDA_SUCCESS);
    }

    if (ok)
        k2_tma<<<dim3(SPLIT, C_ / 128, B_), 256, SMEM_TMA>>>(tmA, tmB, out);
    else
        k2_fb<<<dim3(SPLIT, C_ / 128, B_), 256, SMEM_FB>>>(feats, probs, out);
}

// round 17
// speedup vs baseline: 1.0710x; 1.0710x over previous
#include <cuda_runtime.h>
#include <cuda.h>
#include <cstdint>

#define B_  16
#define K_  29
#define KP  32
#define C_  512
#define S_  16384
#define SPLIT 32
#define KS (S_ / SPLIT)        // 512 s per CTA
#define STILE 32               // s per stage (128 B)
#define NT (KS / STILE)        // 16 stages

// ---- TMA kernel smem layout (SW128, row pitch 32 floats = 128 B) ----
#define SWF 32
#define A_FLOATS (128 * SWF)                 // 4096
#define B_FLOATS (KP * SWF)                  // 1024
#define STAGE_FLOATS (A_FLOATS + B_FLOATS)   // 5120
#define STAGE_BYTES (STAGE_FLOATS * 4)       // 20480
#define SMEM_TMA (2 * STAGE_BYTES + 64)      // + 2 mbarriers, 41 KB -> 5 CTAs/SM

// ---- fallback smem layout ----
#define STRIDE 36
#define AF_FB (128 * STRIDE)
#define BF_FB (KP * STRIDE)
#define STG_FB (AF_FB + BF_FB)
#define SMEM_FB (2 * STG_FB * 4)

#define OUTN (B_ * C_ * K_)

// Per (b,k): 1 / sum(exp(x))
__device__ float g_inv[B_ * KP];

// ---------------- helpers ----------------
__device__ __forceinline__ uint32_t s2u(const void* p) {
    return (uint32_t)__cvta_generic_to_shared(p);
}
__device__ __forceinline__ void cp16(uint32_t dst, const void* src) {
    asm volatile("cp.async.cg.shared.global [%0], [%1], 16;" :: "r"(dst), "l"(src));
}
__device__ __forceinline__ uint32_t totf32(float f) {
    uint32_t r;
    asm("cvt.rna.tf32.f32 %0, %1;" : "=r"(r) : "f"(f));
    return r;
}
__device__ __forceinline__ void mma_tf32(float* d, const uint32_t* a,
                                         const uint32_t* b) {
    asm volatile(
        "mma.sync.aligned.m16n8k8.row.col.f32.tf32.tf32.f32 "
        "{%0,%1,%2,%3}, {%4,%5,%6,%7}, {%8,%9}, {%0,%1,%2,%3};"
        : "+f"(d[0]), "+f"(d[1]), "+f"(d[2]), "+f"(d[3])
        : "r"(a[0]), "r"(a[1]), "r"(a[2]), "r"(a[3]), "r"(b[0]), "r"(b[1]));
}
__device__ __forceinline__ void mbar_init(uint32_t a, uint32_t cnt) {
    asm volatile("mbarrier.init.shared.b64 [%0], %1;" :: "r"(a), "r"(cnt) : "memory");
}
__device__ __forceinline__ void mbar_expect(uint32_t a, uint32_t bytes) {
    asm volatile("mbarrier.arrive.expect_tx.shared.b64 _, [%0], %1;"
                 :: "r"(a), "r"(bytes) : "memory");
}
__device__ __forceinline__ void mbar_wait(uint32_t a, uint32_t ph) {
    asm volatile(
        "{\n\t.reg .pred P1;\n\t"
        "WAIT_LOOP_%=:\n\t"
        "mbarrier.try_wait.parity.acquire.cta.shared::cta.b64 P1, [%0], %1, 0x989680;\n\t"
        "@P1 bra.uni WAIT_DONE_%=;\n\t"
        "bra.uni WAIT_LOOP_%=;\n\t"
        "WAIT_DONE_%=:\n\t}"
        :: "r"(a), "r"(ph) : "memory");
}
__device__ __forceinline__ void tma2d(uint32_t smem, const void* tmap,
                                      int cx, int cy, uint32_t mbar) {
    asm volatile(
        "cp.async.bulk.tensor.2d.shared::cta.global.tile.mbarrier::complete_tx::bytes "
        "[%0], [%1, {%2, %3}], [%4];"
        :: "r"(smem), "l"(tmap), "r"(cx), "r"(cy), "r"(mbar) : "memory");
}

// ---------------- kernel 1: zero out + per-(b,k) 1/sum(exp) ----------------
__global__ __launch_bounds__(256) void k1_stats(const float* __restrict__ probs,
                                                float* __restrict__ out) {
    const int k = blockIdx.x, b = blockIdx.y, tid = threadIdx.x;
    const int gsz = gridDim.x * gridDim.y * 256;
    for (int i = (blockIdx.y * gridDim.x + blockIdx.x) * 256 + tid; i < OUTN; i += gsz)
        out[i] = 0.0f;

    const float4* row = (const float4*)(probs + ((size_t)(b * K_ + k)) * S_);
    __shared__ float red[256];

    float s = 0.0f;
#pragma unroll 4
    for (int i = tid; i < S_ / 4; i += 256) {
        float4 v = row[i];
        s += __expf(v.x) + __expf(v.y) + __expf(v.z) + __expf(v.w);
    }
    red[tid] = s;
    __syncthreads();
    for (int off = 128; off > 0; off >>= 1) {
        if (tid < off) red[tid] += red[tid + off];
        __syncthreads();
    }
    if (tid == 0) g_inv[b * KP + k] = 1.0f / red[0];
}

// ---------------- kernel 2 (TMA): exp-GEMM, normalization in epilogue ----------------
// SPLIT=32 -> grid 2048 = 2.77 waves at 5 CTAs/SM (was 1.38) -> smaller tail.
__global__ __launch_bounds__(256) void k2_tma(
    const __grid_constant__ CUtensorMap tmA,
    const __grid_constant__ CUtensorMap tmB,
    float* __restrict__ out) {
    extern __shared__ float sh[];

    const int tid  = threadIdx.x;
    const int warp = tid >> 5, lane = tid & 31;
    const int b    = blockIdx.z;
    const int cblk = blockIdx.y;
    const int bx   = blockIdx.x;

    const int r = lane >> 2, q = lane & 3;
    const int c0 = warp * 16;

    const int frow = tid >> 3;          // B convert row (0..31)
    const int fcol = tid & 7;           // 16B chunk
    const int fswz = fcol ^ (frow & 7); // swizzled chunk

    const uint32_t sb = s2u(sh);
    const uint32_t MB = sb + 2 * STAGE_BYTES;
    const int rowA0 = b * C_ + cblk * 128;
    const int rowB0 = b * K_;           // rows 29..31 cross-batch/OOB -> discarded cols

    if (tid == 0) { mbar_init(MB, 1); mbar_init(MB + 8, 1); }
    __syncthreads();

    if (tid == 0) {
        asm volatile("fence.proxy.async.shared::cta;" ::: "memory");
        mbar_expect(MB, STAGE_BYTES);
        tma2d(sb, &tmA, bx * STILE, rowA0, MB);
        tma2d(sb + A_FLOATS * 4, &tmB, bx * STILE, rowB0, MB);
    }

    float acc[4][4];
#pragma unroll
    for (int n = 0; n < 4; n++)
#pragma unroll
        for (int i = 0; i < 4; i++) acc[n][i] = 0.0f;

    for (int t = 0; t < NT; t++) {
        const int slot = t & 1;
        if (t + 1 < NT && tid == 0) {
            const int ns = slot ^ 1;
            const int soff = ((t + 1) * SPLIT + bx) * STILE;
            asm volatile("fence.proxy.async.shared::cta;" ::: "memory");
            mbar_expect(MB + ns * 8, STAGE_BYTES);
            tma2d(sb + ns * STAGE_BYTES, &tmA, soff, rowA0, MB + ns * 8);
            tma2d(sb + ns * STAGE_BYTES + A_FLOATS * 4, &tmB, soff, rowB0, MB + ns * 8);
        }
        mbar_wait(MB + slot * 8, (t >> 1) & 1);

        float* Ab = sh + slot * STAGE_FLOATS;
        float* Bb = Ab + A_FLOATS;

        // exp + tf32-convert this thread's 16B chunk of B (no normalization)
        {
            float4* bp = (float4*)(Bb + frow * SWF + fswz * 4);
            float4 v = *bp;
            uint4 w;
            w.x = totf32(__expf(v.x));
            w.y = totf32(__expf(v.y));
            w.z = totf32(__expf(v.z));
            w.w = totf32(__expf(v.w));
            *(uint4*)bp = w;
        }
        __syncthreads();   // B conversions + TMA data visible to all warps

        const uint32_t* A = (const uint32_t*)Ab;   // raw fp32 bits as tf32 (HW truncates)
        const uint32_t* Bm = (const uint32_t*)Bb;
#pragma unroll
        for (int ks = 0; ks < STILE / 8; ks++) {
            const int ch0 = ((2 * ks) ^ r) * 4 + q;       // cols so+q
            const int ch1 = ((2 * ks + 1) ^ r) * 4 + q;   // cols so+q+4
            uint32_t a[4];
            a[0] = A[(c0 + r) * SWF + ch0];
            a[1] = A[(c0 + r + 8) * SWF + ch0];
            a[2] = A[(c0 + r) * SWF + ch1];
            a[3] = A[(c0 + r + 8) * SWF + ch1];
#pragma unroll
            for (int n = 0; n < 4; n++) {
                uint32_t bb[2];
                bb[0] = Bm[(n * 8 + r) * SWF + ch0];
                bb[1] = Bm[(n * 8 + r) * SWF + ch1];
                mma_tf32(acc[n], a, bb);
            }
        }
        __syncthreads();   // slot reads done before reuse
    }

    // ---- epilogue: normalize by 1/sum, then atomicAdd ----
    const int cg = cblk * 128 + c0 + r;
#pragma unroll
    for (int n = 0; n < 4; n++) {
#pragma unroll
        for (int i = 0; i < 4; i++) {
            const int c = cg + (i >> 1) * 8;
            const int k = n * 8 + q * 2 + (i & 1);
            if (k < K_) {
                const float v = acc[n][i] * g_inv[b * KP + k];
                atomicAdd(out + ((size_t)(b * C_ + c)) * K_ + k, v);
            }
        }
    }
}

// ---------------- kernel 2 fallback: cp.async version, same math ----------------
__global__ __launch_bounds__(256) void k2_fb(const float* __restrict__ feats,
                                             const float* __restrict__ probs,
                                             float* __restrict__ out) {
    extern __shared__ float sh[];
    const int tid = threadIdx.x, warp = tid >> 5, lane = tid & 31;
    const int b = blockIdx.z, cblk = blockIdx.y, bx = blockIdx.x;
    const int r = lane >> 2, q = lane & 3, c0 = warp * 16;
    const int frow = tid >> 3, fcol = tid & 7;
    const int kclamp = frow < K_ ? frow : (K_ - 1);
    const float* fbase = feats + ((size_t)(b * C_ + cblk * 128)) * S_;
    const float* pbase = probs + ((size_t)(b * K_ + kclamp)) * S_;
    const uint32_t sh_u = s2u(sh);

    float acc[4][4];
#pragma unroll
    for (int n = 0; n < 4; n++)
#pragma unroll
        for (int i = 0; i < 4; i++) acc[n][i] = 0.0f;

    {
        const int soff = bx * STILE;
#pragma unroll
        for (int i = 0; i < 4; i++) {
            int row = frow + i * 32;
            cp16(sh_u + (row * STRIDE + fcol * 4) * 4,
                 fbase + (size_t)row * S_ + soff + fcol * 4);
        }
        cp16(sh_u + (AF_FB + frow * STRIDE + fcol * 4) * 4, pbase + soff + fcol * 4);
        asm volatile("cp.async.commit_group;");
    }
    for (int t = 0; t < NT; t++) {
        const int buf = t & 1;
        if (t + 1 < NT) {
            const int nbuf = buf ^ 1;
            const int soff = ((t + 1) * SPLIT + bx) * STILE;
#pragma unroll
            for (int i = 0; i < 4; i++) {
                int row = frow + i * 32;
                cp16(sh_u + (nbuf * STG_FB + row * STRIDE + fcol * 4) * 4,
                     fbase + (size_t)row * S_ + soff + fcol * 4);
            }
            cp16(sh_u + (nbuf * STG_FB + AF_FB + frow * STRIDE + fcol * 4) * 4,
                 pbase + soff + fcol * 4);
            asm volatile("cp.async.commit_group;");
            asm volatile("cp.async.wait_group 1;");
        } else {
            asm volatile("cp.async.wait_group 0;");
        }
        float* Ab = sh + buf * STG_FB;
        float* Bb = Ab + AF_FB;
        {
            float4* bp = (float4*)(Bb + frow * STRIDE + fcol * 4);
            float4 v = *bp;
            uint4 w;
            w.x = totf32(__expf(v.x));
            w.y = totf32(__expf(v.y));
            w.z = totf32(__expf(v.z));
            w.w = totf32(__expf(v.w));
            *(uint4*)bp = w;
        }
        __syncthreads();
        const uint32_t* A = (const uint32_t*)Ab;
        const uint32_t* Bm = (const uint32_t*)Bb;
#pragma unroll
        for (int ks = 0; ks < STILE / 8; ks++) {
            const int so = ks * 8;
            uint32_t a[4];
            a[0] = A[(c0 + r) * STRIDE + so + q];
            a[1] = A[(c0 + r + 8) * STRIDE + so + q];
            a[2] = A[(c0 + r) * STRIDE + so + q + 4];
            a[3] = A[(c0 + r + 8) * STRIDE + so + q + 4];
#pragma unroll
            for (int n = 0; n < 4; n++) {
                uint32_t bb[2];
                bb[0] = Bm[(n * 8 + r) * STRIDE + so + q];
                bb[1] = Bm[(n * 8 + r) * STRIDE + so + q + 4];
                mma_tf32(acc[n], a, bb);
            }
        }
        __syncthreads();
    }
    const int cg = cblk * 128 + c0 + r;
#pragma unroll
    for (int n = 0; n < 4; n++) {
#pragma unroll
        for (int i = 0; i < 4; i++) {
            const int c = cg + (i >> 1) * 8;
            const int k = n * 8 + q * 2 + (i & 1);
            if (k < K_) {
                const float v = acc[n][i] * g_inv[b * KP + k];
                atomicAdd(out + ((size_t)(b * C_ + c)) * K_ + k, v);
            }
        }
    }
}

extern "C" void kernel_launch(void* const* d_in, const int* in_sizes, int n_in,
                              void* d_out, int out_size) {
    const float* feats = (const float*)d_in[0];  // (16, 512, 128, 128)
    const float* probs = (const float*)d_in[1];  // (16, 29, 128, 128)
    float* out = (float*)d_out;                  // (16, 512, 29, 1)

    k1_stats<<<dim3(K_, B_), 256>>>(probs, out);

    typedef CUresult (CUDAAPI *EncFn)(
        CUtensorMap*, CUtensorMapDataType, cuuint32_t, void*,
        const cuuint64_t*, const cuuint64_t*, const cuuint32_t*, const cuuint32_t*,
        CUtensorMapInterleave, CUtensorMapSwizzle, CUtensorMapL2promotion,
        CUtensorMapFloatOOBfill);

    void* sym = nullptr;
    cudaDriverEntryPointQueryResult qr = cudaDriverEntryPointSymbolNotFound;
    cudaGetDriverEntryPoint("cuTensorMapEncodeTiled", &sym, cudaEnableDefault, &qr);

    bool ok = false;
    CUtensorMap tmA, tmB;
    if (sym != nullptr && qr == cudaDriverEntryPointSuccess) {
        EncFn enc = (EncFn)sym;
        cuuint64_t dimsA[2] = {(cuuint64_t)S_, (cuuint64_t)(B_ * C_)};
        cuuint64_t strid[1] = {(cuuint64_t)S_ * 4};
        cuuint32_t boxA[2]  = {STILE, 128};
        cuuint32_t ones[2]  = {1, 1};
        CUresult r1 = enc(&tmA, CU_TENSOR_MAP_DATA_TYPE_FLOAT32, 2, (void*)feats,
                          dimsA, strid, boxA, ones,
                          CU_TENSOR_MAP_INTERLEAVE_NONE, CU_TENSOR_MAP_SWIZZLE_128B,
                          CU_TENSOR_MAP_L2_PROMOTION_L2_256B,
                          CU_TENSOR_MAP_FLOAT_OOB_FILL_NONE);
        cuuint64_t dimsB[2] = {(cuuint64_t)S_, (cuuint64_t)(B_ * K_)};
        cuuint32_t boxB[2]  = {STILE, KP};
        CUresult r2 = enc(&tmB, CU_TENSOR_MAP_DATA_TYPE_FLOAT32, 2, (void*)probs,
                          dimsB, strid, boxB, ones,
                          CU_TENSOR_MAP_INTERLEAVE_NONE, CU_TENSOR_MAP_SWIZZLE_128B,
                          CU_TENSOR_MAP_L2_PROMOTION_L2_256B,
                          CU_TENSOR_MAP_FLOAT_OOB_FILL_NONE);
        ok = (r1 == CUDA_SUCCESS) && (r2 == CUDA_SUCCESS);
    }

    if (ok)
        k2_tma<<<dim3(SPLIT, C_ / 128, B_), 256, SMEM_TMA>>>(tmA, tmB, out);
    else
        k2_fb<<<dim3(SPLIT, C_ / 128, B_), 256, SMEM_FB>>>(feats, probs, out);
}